// round 8
// baseline (speedup 1.0000x reference)
#include <cuda_runtime.h>
#include <cstdint>
#include <math.h>

// Problem constants
#define PS   2048
#define PD   64
#define PBH  32
#define TQ   128
#define TK   64
#define NQB  (PS / TQ)     // 16
#define NTH  256

#define OUT_ELEMS   (PBH * PS * PD)
#define PATTN_ELEMS ((size_t)PBH * (size_t)PS * (size_t)PS)

// 129-row sin/cos table (causal => clipped rel index in [0,128])
__device__ float g_table[129 * 64];
// K transposed per head: [bh][d][s]
__device__ float g_KT[(size_t)PBH * PD * PS];
// bias table: g_QR[bh][s][j], j in [0,128], row stride 132
__device__ float g_QR[(size_t)PBH * PS * 132];

// ---------------- f32x2 packed-FMA helpers ----------------
__device__ __forceinline__ unsigned long long pk2(float a, float b) {
    unsigned long long r;
    asm("mov.b64 %0,{%1,%2};" : "=l"(r) : "f"(a), "f"(b));
    return r;
}
__device__ __forceinline__ float2 up2(unsigned long long v) {
    float2 r;
    asm("mov.b64 {%0,%1},%2;" : "=f"(r.x), "=f"(r.y) : "l"(v));
    return r;
}
#define FMA2(d, a, b) asm("fma.rn.f32x2 %0,%1,%2,%0;" : "+l"(d) : "l"(a), "l"(b))

__device__ __forceinline__ unsigned smem_u32(const void* p) {
    return (unsigned)__cvta_generic_to_shared(p);
}
__device__ __forceinline__ void cpa16(unsigned s, const void* g) {
    asm volatile("cp.async.cg.shared.global [%0], [%1], 16;" :: "r"(s), "l"(g));
}

__global__ void init_table_kernel() {
    int j = blockIdx.x;     // 0..128
    int d = threadIdx.x;    // 0..63
    int i2 = d & ~1;
    float div = expf((float)i2 * (-logf(10000.0f) / 64.0f));
    float ang = (float)j * div;
    g_table[j * 64 + d] = (d & 1) ? cosf(ang) : sinf(ang);
}

// One-time K transpose: K[bh][s][d] -> g_KT[bh][d][s]
__global__ void __launch_bounds__(NTH, 4)
transpose_k_kernel(const float* __restrict__ K) {
    __shared__ float t[64 * 68];
    const int tid = threadIdx.x;
    const int st  = blockIdx.x;
    const int bh  = blockIdx.y;
    const float4* Kb = (const float4*)(K + ((size_t)bh * PS + st * 64) * PD);
    #pragma unroll
    for (int i = 0; i < 4; i++) {
        int idx = tid + i * NTH;
        int row = idx >> 4, d4 = idx & 15;
        ((float4*)(t + row * 68))[d4] = Kb[idx];
    }
    __syncthreads();
    #pragma unroll
    for (int i = 0; i < 4; i++) {
        int idx = tid + i * NTH;
        int d = idx >> 4, s4 = idx & 15;
        float4 v;
        v.x = t[(4 * s4 + 0) * 68 + d];
        v.y = t[(4 * s4 + 1) * 68 + d];
        v.z = t[(4 * s4 + 2) * 68 + d];
        v.w = t[(4 * s4 + 3) * 68 + d];
        *(float4*)(g_KT + ((size_t)bh * PD + d) * PS + st * 64 + 4 * s4) = v;
    }
}

// bias pre-kernel: g_QR[bh][s][j] = (Q[bh][s]/8) . T[j]
__global__ void __launch_bounds__(NTH, 4)
bias_kernel(const float* __restrict__ Q) {
    __shared__ float qs[64 * 68];
    __shared__ float tb[129 * 68];
    const int tid = threadIdx.x;
    const int st  = blockIdx.x;
    const int bh  = blockIdx.y;
    {
        const float4* Qb = (const float4*)(Q + ((size_t)bh * PS + st * 64) * PD);
        #pragma unroll
        for (int i = 0; i < 4; i++) {
            int idx = tid + i * NTH;
            int row = idx >> 4, d4 = idx & 15;
            float4 v = Qb[idx];
            v.x *= 0.125f; v.y *= 0.125f; v.z *= 0.125f; v.w *= 0.125f;
            ((float4*)(qs + row * 68))[d4] = v;
        }
        for (int idx = tid; idx < 129 * 16; idx += NTH) {
            int row = idx >> 4, d4 = idx & 15;
            ((float4*)(tb + row * 68))[d4] = ((const float4*)g_table)[idx];
        }
    }
    __syncthreads();
    float* dst = g_QR + ((size_t)bh * PS + st * 64) * 132;
    for (int t = tid; t < 64 * 129; t += NTH) {
        int r = t / 129;
        int j = t - r * 129;
        const float4* qa = (const float4*)(qs + r * 68);
        const float4* ta = (const float4*)(tb + j * 68);
        float acc = 0.0f;
        #pragma unroll
        for (int d4 = 0; d4 < 16; d4++) {
            float4 a = qa[d4], b = ta[d4];
            acc += a.x * b.x + a.y * b.y + a.z * b.z + a.w * b.w;
        }
        dst[r * 132 + j] = acc;
    }
}

// ---------------- smem layout (floats), total 25728 = 102,912 B ----------------
#define OFF_QT 0        // [64][136]  Q^T (prescaled 1/8), d-major, 128 rows
#define OFF_KT 8704     // [64][68]   K^T tile
#define OFF_VS 13056    // [64][68]   V tile natural
#define OFF_PT 17408    // [64][128]  e^T tile, XOR-swizzled 4-row groups
#define OFF_LR 25600    // [128]      1/l
#define SM_TOT 25728

__global__ void __launch_bounds__(NTH, 2)
attn_relpos_kernel(const float* __restrict__ Q,
                   const float* __restrict__ V,
                   float* __restrict__ out,
                   float* __restrict__ P)
{
    extern __shared__ float sm[];
    float* QT = sm + OFF_QT;
    float* KT = sm + OFF_KT;
    float* VS = sm + OFF_VS;
    float* PT = sm + OFF_PT;
    float* LR = sm + OFF_LR;

    const int tid = threadIdx.x;
    const int bh  = blockIdx.x;
    const int qt  = (NQB - 1) - blockIdx.y;   // heavy tiles first
    const int q0  = qt * TQ;
    const int tx  = tid & 15;
    const int ty  = tid >> 4;
    const int tx4 = tx * 4;
    const int ty8 = ty * 8;
    const int nkt = 2 * qt + 2;               // causal 64-wide k-tiles

    // ---------- Q load (prescaled 1/8) -> QT transposed [d][row] ----------
    {
        const float4* Qb = (const float4*)(Q + ((size_t)bh * PS + q0) * PD);
        #pragma unroll
        for (int i = 0; i < 8; i++) {
            int idx = tid + i * NTH;          // 0..2047
            int row = idx >> 4, d4 = idx & 15;
            float4 v = Qb[idx];
            int db = d4 * 4;
            QT[(db + 0) * 136 + row] = v.x * 0.125f;
            QT[(db + 1) * 136 + row] = v.y * 0.125f;
            QT[(db + 2) * 136 + row] = v.z * 0.125f;
            QT[(db + 3) * 136 + row] = v.w * 0.125f;
        }
    }

    // per-row bias base + far-tile factors (L2-resident)
    const float* qr0 = g_QR + ((size_t)bh * PS + q0 + ty8) * 132;
    float rf[8];
    #pragma unroll
    for (int rr = 0; rr < 8; rr++) rf[rr] = __expf(qr0[rr * 132]);

    unsigned long long O2[4][4];   // [row-pair][dcol]
    #pragma unroll
    for (int rp = 0; rp < 4; rp++)
        #pragma unroll
        for (int cc = 0; cc < 4; cc++) O2[rp][cc] = 0ull;
    float lp[8] = {0.f, 0.f, 0.f, 0.f, 0.f, 0.f, 0.f, 0.f};

    const size_t rowbase = (size_t)bh * PS + q0;
    const unsigned ktA = smem_u32(KT);
    const unsigned vsA = smem_u32(VS);
    const float* KTg0 = g_KT + (size_t)bh * PD * PS;
    const float* Vg0  = V + (size_t)bh * PS * PD;

    for (int kt = 0; kt < nkt; kt++) {
        __syncthreads();   // prior PV done with KT/VS
        // async-load K^T and V tiles
        {
            const float* KTg = KTg0 + kt * TK;
            const float* Vg  = Vg0 + (size_t)kt * TK * PD;
            #pragma unroll
            for (int i = 0; i < 4; i++) {
                int idx = tid + i * NTH;
                int a = idx >> 4, b4 = idx & 15;
                cpa16(ktA + (a * 68 + b4 * 4) * 4, KTg + (size_t)a * PS + b4 * 4);
                cpa16(vsA + (a * 68 + b4 * 4) * 4, Vg + idx * 4);
            }
        }
        asm volatile("cp.async.commit_group;");
        asm volatile("cp.async.wait_group 0;");
        __syncthreads();

        // -------- QK GEMM: 8 rows (4 packed pairs) x 4 cols --------
        unsigned long long acc[4][4];
        #pragma unroll
        for (int rp = 0; rp < 4; rp++)
            #pragma unroll
            for (int cc = 0; cc < 4; cc++) acc[rp][cc] = 0ull;

        #pragma unroll 16
        for (int d = 0; d < 64; d++) {
            const float* qb = QT + d * 136 + ty8;
            ulonglong2 qa = *(const ulonglong2*)qb;         // rows (0,1),(2,3)
            ulonglong2 qc = *(const ulonglong2*)(qb + 4);   // rows (4,5),(6,7)
            float4 kv = *(const float4*)(KT + d * 68 + tx4);
            unsigned long long k0 = pk2(kv.x, kv.x), k1 = pk2(kv.y, kv.y);
            unsigned long long k2 = pk2(kv.z, kv.z), k3 = pk2(kv.w, kv.w);
            FMA2(acc[0][0], qa.x, k0); FMA2(acc[0][1], qa.x, k1);
            FMA2(acc[0][2], qa.x, k2); FMA2(acc[0][3], qa.x, k3);
            FMA2(acc[1][0], qa.y, k0); FMA2(acc[1][1], qa.y, k1);
            FMA2(acc[1][2], qa.y, k2); FMA2(acc[1][3], qa.y, k3);
            FMA2(acc[2][0], qc.x, k0); FMA2(acc[2][1], qc.x, k1);
            FMA2(acc[2][2], qc.x, k2); FMA2(acc[2][3], qc.x, k3);
            FMA2(acc[3][0], qc.y, k0); FMA2(acc[3][1], qc.y, k1);
            FMA2(acc[3][2], qc.y, k2); FMA2(acc[3][3], qc.y, k3);
        }

        // -------- scores -> e, in two 4-row halves (register economy) --------
        const bool far = (kt * TK + 191 <= q0);
        const int swz = tx & 7;   // (c>>2)&7 for c = tx4+cc
        #pragma unroll
        for (int h2 = 0; h2 < 2; h2++) {
            float e[4][4];
            #pragma unroll
            for (int cc = 0; cc < 4; cc++) {
                float2 lo = up2(acc[2 * h2][cc]);
                float2 hi = up2(acc[2 * h2 + 1][cc]);
                e[0][cc] = lo.x; e[1][cc] = lo.y;
                e[2][cc] = hi.x; e[3][cc] = hi.y;
            }
            if (far) {
                #pragma unroll
                for (int rl = 0; rl < 4; rl++) {
                    float f = rf[4 * h2 + rl];
                    #pragma unroll
                    for (int cc = 0; cc < 4; cc++)
                        e[rl][cc] = f * __expf(e[rl][cc]);
                }
            } else {
                #pragma unroll
                for (int rl = 0; rl < 4; rl++) {
                    int R = ty8 + 4 * h2 + rl;
                    const float* qr = qr0 + (4 * h2 + rl) * 132;
                    int jbase = kt * TK + tx4 - (q0 + R) + 128;
                    #pragma unroll
                    for (int cc = 0; cc < 4; cc++) {
                        int jr = jbase + cc;
                        float ev = 0.0f;
                        if (jr <= 128) {
                            int jc = jr < 0 ? 0 : jr;
                            ev = __expf(e[rl][cc] + qr[jc]);
                        }
                        e[rl][cc] = ev;
                    }
                }
            }
            #pragma unroll
            for (int rl = 0; rl < 4; rl++)
                lp[4 * h2 + rl] += (e[rl][0] + e[rl][1]) + (e[rl][2] + e[rl][3]);

            // unnormalized e -> global P
            if (P) {
                #pragma unroll
                for (int rl = 0; rl < 4; rl++) {
                    *(float4*)(P + (rowbase + ty8 + 4 * h2 + rl) * (size_t)PS
                               + kt * TK + tx4) =
                        make_float4(e[rl][0], e[rl][1], e[rl][2], e[rl][3]);
                }
            }
            // e^T into PT: logical 4-row group g stored at slot g^swz
            {
                int gs = (2 * ty + h2) ^ swz;
                #pragma unroll
                for (int cc = 0; cc < 4; cc++) {
                    *(float4*)(PT + (tx4 + cc) * 128 + 4 * gs) =
                        make_float4(e[0][cc], e[1][cc], e[2][cc], e[3][cc]);
                }
            }
        }
        __syncthreads();   // PT complete

        // -------- PV GEMM (swizzle constants compile-time via full unroll) --------
        #pragma unroll
        for (int cb = 0; cb < 64; cb += 32) {
            #pragma unroll
            for (int c4 = 0; c4 < 8; c4++) {
                const int sw = c4;   // ((cb+4*c4)>>2)&7 == c4 for cb multiple of 32
                const float* base = PT + (cb + 4 * c4) * 128;
                #pragma unroll
                for (int ci = 0; ci < 4; ci++) {
                    int c = cb + 4 * c4 + ci;
                    ulonglong2 pa;
                    pa.x = *(const unsigned long long*)(base + ci * 128 + 4 * ((2 * ty) ^ sw));
                    pa.y = *(const unsigned long long*)(base + ci * 128 + 4 * ((2 * ty) ^ sw) + 2);
                    ulonglong2 pc;
                    pc.x = *(const unsigned long long*)(base + ci * 128 + 4 * ((2 * ty + 1) ^ sw));
                    pc.y = *(const unsigned long long*)(base + ci * 128 + 4 * ((2 * ty + 1) ^ sw) + 2);
                    float4 vv = *(const float4*)(VS + c * 68 + tx4);
                    unsigned long long v0 = pk2(vv.x, vv.x), v1 = pk2(vv.y, vv.y);
                    unsigned long long v2 = pk2(vv.z, vv.z), v3 = pk2(vv.w, vv.w);
                    FMA2(O2[0][0], pa.x, v0); FMA2(O2[0][1], pa.x, v1);
                    FMA2(O2[0][2], pa.x, v2); FMA2(O2[0][3], pa.x, v3);
                    FMA2(O2[1][0], pa.y, v0); FMA2(O2[1][1], pa.y, v1);
                    FMA2(O2[1][2], pa.y, v2); FMA2(O2[1][3], pa.y, v3);
                    FMA2(O2[2][0], pc.x, v0); FMA2(O2[2][1], pc.x, v1);
                    FMA2(O2[2][2], pc.x, v2); FMA2(O2[2][3], pc.x, v3);
                    FMA2(O2[3][0], pc.y, v0); FMA2(O2[3][1], pc.y, v1);
                    FMA2(O2[3][2], pc.y, v2); FMA2(O2[3][3], pc.y, v3);
                }
            }
        }
    }

    // ---------- row sums -> 1/l ----------
    #pragma unroll
    for (int off = 1; off < 16; off <<= 1)
        #pragma unroll
        for (int rr = 0; rr < 8; rr++)
            lp[rr] += __shfl_xor_sync(0xffffffffu, lp[rr], off, 16);
    float linv[8];
    #pragma unroll
    for (int rr = 0; rr < 8; rr++) linv[rr] = 1.0f / lp[rr];
    if (tx == 0) {
        #pragma unroll
        for (int rr = 0; rr < 8; rr++) LR[ty8 + rr] = linv[rr];
    }
    __syncthreads();   // LR + this block's P writes visible in-block

    // ---------- epilogue: rel-V via softmax identity (band from global P) ----------
    if (P) {
        const float4* Tg = (const float4*)g_table;
        float4 tb0 = Tg[tx];
        #pragma unroll
        for (int h2 = 0; h2 < 2; h2++) {
            float rel[4][4];
            #pragma unroll
            for (int rl = 0; rl < 4; rl++)
                #pragma unroll
                for (int cc = 0; cc < 4; cc++) rel[rl][cc] = 0.0f;

            for (int j = 1; j <= 128; j++) {
                float4 tj = Tg[j * 16 + tx];
                float dx = tj.x - tb0.x, dy = tj.y - tb0.y;
                float dz = tj.z - tb0.z, dw = tj.w - tb0.w;
                #pragma unroll
                for (int rl = 0; rl < 4; rl++) {
                    int R = ty8 + 4 * h2 + rl;
                    int col = q0 + R - 128 + j;
                    if (col >= 0) {
                        float pv = P[(rowbase + R) * (size_t)PS + col];
                        rel[rl][0] += pv * dx;
                        rel[rl][1] += pv * dy;
                        rel[rl][2] += pv * dz;
                        rel[rl][3] += pv * dw;
                    }
                }
            }
            #pragma unroll
            for (int rl = 0; rl < 4; rl++) {
                int rp = 2 * h2 + (rl >> 1);
                float o[4];
                #pragma unroll
                for (int cc = 0; cc < 4; cc++) {
                    float2 t = up2(O2[rp][cc]);
                    o[cc] = (rl & 1) ? t.y : t.x;
                }
                float li = linv[4 * h2 + rl];
                float4 res;
                res.x = (o[0] + rel[rl][0]) * li + tb0.x;
                res.y = (o[1] + rel[rl][1]) * li + tb0.y;
                res.z = (o[2] + rel[rl][2]) * li + tb0.z;
                res.w = (o[3] + rel[rl][3]) * li + tb0.w;
                *(float4*)(out + (rowbase + ty8 + 4 * h2 + rl) * PD + tx4) = res;
            }
        }
    }
    __syncthreads();   // band reads done before P rescale

    // ---------- normalize P rows; zero-fill never-written region ----------
    if (P) {
        const int nt4 = nkt * 16;
        for (int idx = tid; idx < TQ * (PS / 4); idx += NTH) {
            int row = idx >> 9;
            int c4  = idx & 511;
            float4* pp = (float4*)(P + (rowbase + row) * (size_t)PS) + c4;
            if (c4 < nt4) {
                float s = LR[row];
                float4 v = *pp;
                v.x *= s; v.y *= s; v.z *= s; v.w *= s;
                *pp = v;
            } else {
                *pp = make_float4(0.f, 0.f, 0.f, 0.f);
            }
        }
    }
}

extern "C" void kernel_launch(void* const* d_in, const int* in_sizes, int n_in,
                              void* d_out, int out_size) {
    const float* Q = (const float*)d_in[0];
    const float* K = (const float*)d_in[1];
    const float* V = (const float*)d_in[2];

    float* out = (float*)d_out;
    float* P = nullptr;
    if ((size_t)out_size >= (size_t)OUT_ELEMS + PATTN_ELEMS)
        P = out + OUT_ELEMS;

    init_table_kernel<<<129, 64>>>();
    {
        dim3 tg(PS / 64, PBH);
        transpose_k_kernel<<<tg, NTH>>>(K);
        bias_kernel<<<tg, NTH>>>(Q);
    }

    size_t smem_bytes = SM_TOT * sizeof(float);
    cudaFuncSetAttribute(attn_relpos_kernel,
                         cudaFuncAttributeMaxDynamicSharedMemorySize,
                         (int)smem_bytes);
    dim3 grid(PBH, NQB);
    attn_relpos_kernel<<<grid, NTH, smem_bytes>>>(Q, V, out, P);
}

// round 10
// speedup vs baseline: 1.1937x; 1.1937x over previous
#include <cuda_runtime.h>
#include <cstdint>
#include <math.h>

// Problem constants
#define PS   2048
#define PD   64
#define PBH  32
#define TQ   64
#define TK   64
#define NQB  (PS / TQ)     // 32
#define NTH  256

#define OUT_ELEMS   (PBH * PS * PD)
#define PATTN_ELEMS ((size_t)PBH * (size_t)PS * (size_t)PS)

// 129-row sin/cos table (causal => clipped rel index in [0,128])
__device__ float g_table[129 * 64];
// K transposed per head: [bh][d][s]
__device__ float g_KT[(size_t)PBH * PD * PS];
// bias table: g_QR[bh][s][j], j in [0,128], row stride 132
__device__ float g_QR[(size_t)PBH * PS * 132];

// ---------------- f32x2 packed-FMA helpers ----------------
__device__ __forceinline__ unsigned long long pk2(float a, float b) {
    unsigned long long r;
    asm("mov.b64 %0,{%1,%2};" : "=l"(r) : "f"(a), "f"(b));
    return r;
}
__device__ __forceinline__ float2 up2(unsigned long long v) {
    float2 r;
    asm("mov.b64 {%0,%1},%2;" : "=f"(r.x), "=f"(r.y) : "l"(v));
    return r;
}
#define FMA2(d, a, b) asm("fma.rn.f32x2 %0,%1,%2,%0;" : "+l"(d) : "l"(a), "l"(b))

__device__ __forceinline__ unsigned smem_u32(const void* p) {
    return (unsigned)__cvta_generic_to_shared(p);
}
__device__ __forceinline__ void cpa16(unsigned s, const void* g) {
    asm volatile("cp.async.cg.shared.global [%0], [%1], 16;" :: "r"(s), "l"(g));
}

__global__ void init_table_kernel() {
    int j = blockIdx.x;     // 0..128
    int d = threadIdx.x;    // 0..63
    int i2 = d & ~1;
    float div = expf((float)i2 * (-logf(10000.0f) / 64.0f));
    float ang = (float)j * div;
    g_table[j * 64 + d] = (d & 1) ? cosf(ang) : sinf(ang);
}

// One-time K transpose: K[bh][s][d] -> g_KT[bh][d][s]
__global__ void __launch_bounds__(NTH, 4)
transpose_k_kernel(const float* __restrict__ K) {
    __shared__ float t[64 * 68];
    const int tid = threadIdx.x;
    const int st  = blockIdx.x;
    const int bh  = blockIdx.y;
    const float4* Kb = (const float4*)(K + ((size_t)bh * PS + st * 64) * PD);
    #pragma unroll
    for (int i = 0; i < 4; i++) {
        int idx = tid + i * NTH;
        int row = idx >> 4, d4 = idx & 15;
        ((float4*)(t + row * 68))[d4] = Kb[idx];
    }
    __syncthreads();
    #pragma unroll
    for (int i = 0; i < 4; i++) {
        int idx = tid + i * NTH;
        int d = idx >> 4, s4 = idx & 15;
        float4 v;
        v.x = t[(4 * s4 + 0) * 68 + d];
        v.y = t[(4 * s4 + 1) * 68 + d];
        v.z = t[(4 * s4 + 2) * 68 + d];
        v.w = t[(4 * s4 + 3) * 68 + d];
        *(float4*)(g_KT + ((size_t)bh * PD + d) * PS + st * 64 + 4 * s4) = v;
    }
}

// bias pre-kernel: g_QR[bh][s][j] = (Q[bh][s]/8) . T[j]
__global__ void __launch_bounds__(NTH, 4)
bias_kernel(const float* __restrict__ Q) {
    __shared__ float qs[64 * 68];
    __shared__ float tb[129 * 68];
    const int tid = threadIdx.x;
    const int st  = blockIdx.x;
    const int bh  = blockIdx.y;
    {
        const float4* Qb = (const float4*)(Q + ((size_t)bh * PS + st * 64) * PD);
        #pragma unroll
        for (int i = 0; i < 4; i++) {
            int idx = tid + i * NTH;
            int row = idx >> 4, d4 = idx & 15;
            float4 v = Qb[idx];
            v.x *= 0.125f; v.y *= 0.125f; v.z *= 0.125f; v.w *= 0.125f;
            ((float4*)(qs + row * 68))[d4] = v;
        }
        for (int idx = tid; idx < 129 * 16; idx += NTH) {
            int row = idx >> 4, d4 = idx & 15;
            ((float4*)(tb + row * 68))[d4] = ((const float4*)g_table)[idx];
        }
    }
    __syncthreads();
    float* dst = g_QR + ((size_t)bh * PS + st * 64) * 132;
    for (int t = tid; t < 64 * 129; t += NTH) {
        int r = t / 129;
        int j = t - r * 129;
        const float4* qa = (const float4*)(qs + r * 68);
        const float4* ta = (const float4*)(tb + j * 68);
        float acc = 0.0f;
        #pragma unroll
        for (int d4 = 0; d4 < 16; d4++) {
            float4 a = qa[d4], b = ta[d4];
            acc += a.x * b.x + a.y * b.y + a.z * b.z + a.w * b.w;
        }
        dst[r * 132 + j] = acc;
    }
}

// ---------------- smem layout (floats), total 16704 = 66,816 B ----------------
#define OFF_QT 0        // [64][68]  Q^T (prescaled 1/8), d-major
#define OFF_KT 4352     // [64][64]  K^T tile
#define OFF_VS 8448     // [64][64]  V tile natural
#define OFF_PT 12544    // [64][64]  e^T tile, XOR-slot swizzled
#define OFF_LR 16640    // [64]      1/l
#define SM_TOT 16704
// epilogue band overlay: [64][132] at OFF_KT (needs 8448 <= 12288)

__global__ void __launch_bounds__(NTH, 3)
attn_relpos_kernel(const float* __restrict__ Q,
                   const float* __restrict__ V,
                   float* __restrict__ out,
                   float* __restrict__ P)
{
    extern __shared__ float sm[];
    float* QT = sm + OFF_QT;
    float* KT = sm + OFF_KT;
    float* VS = sm + OFF_VS;
    float* PT = sm + OFF_PT;
    float* LR = sm + OFF_LR;

    const int tid = threadIdx.x;
    const int bh  = blockIdx.x;
    const int qt  = (NQB - 1) - blockIdx.y;   // heavy tiles first
    const int q0  = qt * TQ;
    const int tx  = tid & 15;
    const int ty  = tid >> 4;
    const int tx4 = tx * 4;
    const int ty4 = ty * 4;
    const int nkt = qt + 1;

    // ---------- Q load (prescaled 1/8) -> QT transposed ----------
    {
        const float4* Qb = (const float4*)(Q + ((size_t)bh * PS + q0) * PD);
        #pragma unroll
        for (int i = 0; i < 4; i++) {
            int idx = tid + i * NTH;
            int row = idx >> 4, d4 = idx & 15;
            float4 v = Qb[idx];
            int db = d4 * 4;
            QT[(db + 0) * 68 + row] = v.x * 0.125f;
            QT[(db + 1) * 68 + row] = v.y * 0.125f;
            QT[(db + 2) * 68 + row] = v.z * 0.125f;
            QT[(db + 3) * 68 + row] = v.w * 0.125f;
        }
    }

    // per-row far-tile factor + bias row pointers (L2-resident)
    const float* qrRow[4];
    float rf[4];
    #pragma unroll
    for (int rr = 0; rr < 4; rr++) {
        qrRow[rr] = g_QR + ((size_t)bh * PS + q0 + ty4 + rr) * 132;
        rf[rr] = __expf(qrRow[rr][0]);
    }

    unsigned long long O2[4][2];
    #pragma unroll
    for (int rr = 0; rr < 4; rr++) { O2[rr][0] = 0ull; O2[rr][1] = 0ull; }
    float lp[4] = {0.f, 0.f, 0.f, 0.f};

    const size_t rowbase = (size_t)bh * PS + q0;
    const unsigned ktA = smem_u32(KT);
    const unsigned vsA = smem_u32(VS);
    const float* KTg0 = g_KT + (size_t)bh * PD * PS;
    const float* Vg0  = V + (size_t)bh * PS * PD;
    const int ptSlot = 4 * (ty ^ (tx & 7));   // e^T store slot (swizzled)

    for (int kt = 0; kt < nkt; kt++) {
        __syncthreads();   // prior GEMMs done with KT/VS
        // async-load K^T tile (group 0), then V tile (group 1)
        {
            const float* KTg = KTg0 + kt * TK;
            #pragma unroll
            for (int i = 0; i < 4; i++) {
                int idx = tid + i * NTH;
                int a = idx >> 4, b4 = idx & 15;
                cpa16(ktA + (a * 64 + b4 * 4) * 4, KTg + (size_t)a * PS + b4 * 4);
            }
            asm volatile("cp.async.commit_group;");
            const float* Vg = Vg0 + (size_t)kt * TK * PD;
            #pragma unroll
            for (int i = 0; i < 4; i++) {
                int idx = tid + i * NTH;
                int a = idx >> 4, b4 = idx & 15;
                cpa16(vsA + (a * 64 + b4 * 4) * 4, Vg + idx * 4);
            }
            asm volatile("cp.async.commit_group;");
        }
        asm volatile("cp.async.wait_group 1;");   // KT ready; VS may be in flight
        __syncthreads();

        // -------- QK GEMM --------
        unsigned long long acc[4][2];
        #pragma unroll
        for (int rr = 0; rr < 4; rr++) { acc[rr][0] = 0ull; acc[rr][1] = 0ull; }

        #pragma unroll 16
        for (int d = 0; d < 64; d++) {
            float4 qv = *(const float4*)(QT + d * 68 + ty4);
            ulonglong2 kp = *(const ulonglong2*)(KT + d * 64 + tx4);
            unsigned long long qd0 = pk2(qv.x, qv.x), qd1 = pk2(qv.y, qv.y);
            unsigned long long qd2 = pk2(qv.z, qv.z), qd3 = pk2(qv.w, qv.w);
            FMA2(acc[0][0], qd0, kp.x); FMA2(acc[0][1], qd0, kp.y);
            FMA2(acc[1][0], qd1, kp.x); FMA2(acc[1][1], qd1, kp.y);
            FMA2(acc[2][0], qd2, kp.x); FMA2(acc[2][1], qd2, kp.y);
            FMA2(acc[3][0], qd3, kp.x); FMA2(acc[3][1], qd3, kp.y);
        }

        // -------- scores -> e --------
        float er[4][4];
        #pragma unroll
        for (int rr = 0; rr < 4; rr++) {
            float2 a = up2(acc[rr][0]), b = up2(acc[rr][1]);
            er[rr][0] = a.x; er[rr][1] = a.y; er[rr][2] = b.x; er[rr][3] = b.y;
        }

        if (kt * TK + 191 <= q0) {
            #pragma unroll
            for (int rr = 0; rr < 4; rr++)
                #pragma unroll
                for (int cc = 0; cc < 4; cc++)
                    er[rr][cc] = rf[rr] * __expf(er[rr][cc]);
        } else {
            #pragma unroll
            for (int rr = 0; rr < 4; rr++) {
                int R = ty4 + rr;
                int jbase = kt * TK + tx4 - (q0 + R) + 128;
                #pragma unroll
                for (int cc = 0; cc < 4; cc++) {
                    int jr = jbase + cc;
                    float ev = 0.0f;
                    if (jr <= 128) {
                        int jc = jr < 0 ? 0 : jr;
                        ev = __expf(er[rr][cc] + qrRow[rr][jc]);
                    }
                    er[rr][cc] = ev;
                }
            }
        }
        #pragma unroll
        for (int rr = 0; rr < 4; rr++)
            lp[rr] += (er[rr][0] + er[rr][1]) + (er[rr][2] + er[rr][3]);

        // unnormalized e -> global P
        if (P) {
            #pragma unroll
            for (int rr = 0; rr < 4; rr++) {
                *(float4*)(P + (rowbase + ty4 + rr) * (size_t)PS + kt * TK + tx4) =
                    make_float4(er[rr][0], er[rr][1], er[rr][2], er[rr][3]);
            }
        }
        // e transposed into PT (conflict-free swizzled slots)
        #pragma unroll
        for (int cc = 0; cc < 4; cc++) {
            *(float4*)(PT + (tx4 + cc) * 64 + ptSlot) =
                make_float4(er[0][cc], er[1][cc], er[2][cc], er[3][cc]);
        }
        asm volatile("cp.async.wait_group 0;");   // VS ready
        __syncthreads();

        // -------- PV GEMM (swizzle constant per 4-col group) --------
        #pragma unroll 4
        for (int c4 = 0; c4 < 16; c4++) {
            const int sw = 4 * (ty ^ (c4 & 7));
            #pragma unroll
            for (int ci = 0; ci < 4; ci++) {
                int c = 4 * c4 + ci;
                float4 pv = *(const float4*)(PT + c * 64 + sw);
                ulonglong2 vp = *(const ulonglong2*)(VS + c * 64 + tx4);
                unsigned long long pd0 = pk2(pv.x, pv.x), pd1 = pk2(pv.y, pv.y);
                unsigned long long pd2 = pk2(pv.z, pv.z), pd3 = pk2(pv.w, pv.w);
                FMA2(O2[0][0], pd0, vp.x); FMA2(O2[0][1], pd0, vp.y);
                FMA2(O2[1][0], pd1, vp.x); FMA2(O2[1][1], pd1, vp.y);
                FMA2(O2[2][0], pd2, vp.x); FMA2(O2[2][1], pd2, vp.y);
                FMA2(O2[3][0], pd3, vp.x); FMA2(O2[3][1], pd3, vp.y);
            }
        }
    }

    // ---------- row sums -> 1/l ----------
    #pragma unroll
    for (int off = 1; off < 16; off <<= 1)
        #pragma unroll
        for (int rr = 0; rr < 4; rr++)
            lp[rr] += __shfl_xor_sync(0xffffffffu, lp[rr], off, 16);
    float linv[4];
    #pragma unroll
    for (int rr = 0; rr < 4; rr++) linv[rr] = 1.0f / lp[rr];
    if (tx == 0) {
        #pragma unroll
        for (int rr = 0; rr < 4; rr++) LR[ty4 + rr] = linv[rr];
    }
    __syncthreads();   // LR visible; all GEMM smem reads complete

    // ---------- fill diagonal band into smem (overlay on KT/VS/PT) ----------
    float* BAND = sm + OFF_KT;   // [64][132]
    if (P) {
        for (int t = tid; t < 64 * 33; t += NTH) {
            int r  = t / 33;
            int i4 = t - r * 33;
            int A  = (q0 + r - 127) & ~3;   // aligned base col (can be <0)
            int col = A + 4 * i4;
            const float* Prow = P + (rowbase + r) * (size_t)PS;
            float4 v;
            if (col >= 0 && col + 3 < PS) {
                v = *(const float4*)(Prow + col);
            } else {
                v.x = (col + 0 >= 0 && col + 0 < PS) ? Prow[col + 0] : 0.f;
                v.y = (col + 1 >= 0 && col + 1 < PS) ? Prow[col + 1] : 0.f;
                v.z = (col + 2 >= 0 && col + 2 < PS) ? Prow[col + 2] : 0.f;
                v.w = (col + 3 >= 0 && col + 3 < PS) ? Prow[col + 3] : 0.f;
            }
            *(float4*)(BAND + r * 132 + 4 * i4) = v;
        }
    }
    __syncthreads();

    // ---------- epilogue: rel-V via softmax identity (band from smem) ----------
    if (P) {
        float rel[4][4];
        #pragma unroll
        for (int rr = 0; rr < 4; rr++)
            #pragma unroll
            for (int cc = 0; cc < 4; cc++) rel[rr][cc] = 0.0f;

        const float* bptr[4];
        #pragma unroll
        for (int rr = 0; rr < 4; rr++) {
            int r = ty4 + rr;
            int off0 = (q0 + r - 127) & 3;
            bptr[rr] = BAND + r * 132 + off0;   // index j-1 for j=1..128
        }

        const float4* Tg = (const float4*)g_table;
        float4 tb0 = Tg[tx];
        for (int j = 1; j <= 128; j++) {
            float4 tj = Tg[j * 16 + tx];
            float dx = tj.x - tb0.x, dy = tj.y - tb0.y;
            float dz = tj.z - tb0.z, dw = tj.w - tb0.w;
            #pragma unroll
            for (int rr = 0; rr < 4; rr++) {
                float pv = bptr[rr][j - 1];
                rel[rr][0] += pv * dx;
                rel[rr][1] += pv * dy;
                rel[rr][2] += pv * dz;
                rel[rr][3] += pv * dw;
            }
        }
        #pragma unroll
        for (int rr = 0; rr < 4; rr++) {
            float2 a = up2(O2[rr][0]), b = up2(O2[rr][1]);
            float4 res;
            res.x = (a.x + rel[rr][0]) * linv[rr] + tb0.x;
            res.y = (a.y + rel[rr][1]) * linv[rr] + tb0.y;
            res.z = (b.x + rel[rr][2]) * linv[rr] + tb0.z;
            res.w = (b.y + rel[rr][3]) * linv[rr] + tb0.w;
            *(float4*)(out + (rowbase + ty4 + rr) * PD + tx4) = res;
        }
    }

    // ---------- normalize P rows; zero-fill never-written region ----------
    if (P) {
        const int nt4 = nkt * 16;
        for (int idx = tid; idx < 64 * (PS / 4); idx += NTH) {
            int row = idx >> 9;
            int c4  = idx & 511;
            float4* pp = (float4*)(P + (rowbase + row) * (size_t)PS) + c4;
            if (c4 < nt4) {
                float s = LR[row];
                float4 v = *pp;
                v.x *= s; v.y *= s; v.z *= s; v.w *= s;
                *pp = v;
            } else {
                *pp = make_float4(0.f, 0.f, 0.f, 0.f);
            }
        }
    }
}

extern "C" void kernel_launch(void* const* d_in, const int* in_sizes, int n_in,
                              void* d_out, int out_size) {
    const float* Q = (const float*)d_in[0];
    const float* K = (const float*)d_in[1];
    const float* V = (const float*)d_in[2];

    float* out = (float*)d_out;
    float* P = nullptr;
    if ((size_t)out_size >= (size_t)OUT_ELEMS + PATTN_ELEMS)
        P = out + OUT_ELEMS;

    init_table_kernel<<<129, 64>>>();
    {
        dim3 tg(PS / 64, PBH);
        transpose_k_kernel<<<tg, NTH>>>(K);
        bias_kernel<<<tg, NTH>>>(Q);
    }

    size_t smem_bytes = SM_TOT * sizeof(float);
    cudaFuncSetAttribute(attn_relpos_kernel,
                         cudaFuncAttributeMaxDynamicSharedMemorySize,
                         (int)smem_bytes);
    dim3 grid(PBH, NQB);
    attn_relpos_kernel<<<grid, NTH, smem_bytes>>>(Q, V, out, P);
}